// round 12
// baseline (speedup 1.0000x reference)
#include <cuda_runtime.h>
#include <cuda_bf16.h>
#include <math_constants.h>
#include <cstdint>

// Problem constants
#define NU   8192
#define NL   8192     // per half
#define DD   512
#define CC   1000
#define INV_TAU 10.0f

// ---------------- device scratch ---------------------------------------------
__device__ __nv_bfloat16 g_aqh [NU * DD];
__device__ __nv_bfloat16 g_pqh [NU * DD];
__device__ __nv_bfloat16 g_suph[2 * NL * DD];     // class-sorted order
__device__ float g_rowsum[2 * NU];
__device__ int   g_labels[2 * NL];
__device__ int   g_offsets[2 * (CC + 1)];
__device__ int   g_perm[2 * NL];

// ---------------- PTX helpers -------------------------------------------------
__device__ __forceinline__ uint32_t smem_u32(const void* p) {
    uint32_t a;
    asm("{ .reg .u64 t; cvta.to.shared.u64 t, %1; cvt.u32.u64 %0, t; }" : "=r"(a) : "l"(p));
    return a;
}
#define CP_ASYNC16(s, g) asm volatile("cp.async.cg.shared.global [%0], [%1], 16;" :: "r"(s), "l"(g))
#define CP_COMMIT()      asm volatile("cp.async.commit_group;" ::: "memory")
#define CP_WAIT(n)       asm volatile("cp.async.wait_group %0;" :: "n"(n) : "memory")

__device__ __forceinline__ void ldsm_x4(uint32_t* r, uint32_t addr) {
    asm volatile("ldmatrix.sync.aligned.m8n8.x4.shared.b16 {%0,%1,%2,%3}, [%4];"
        : "=r"(r[0]), "=r"(r[1]), "=r"(r[2]), "=r"(r[3]) : "r"(addr));
}
__device__ __forceinline__ void ldsm_x2(uint32_t* r, uint32_t addr) {
    asm volatile("ldmatrix.sync.aligned.m8n8.x2.shared.b16 {%0,%1}, [%2];"
        : "=r"(r[0]), "=r"(r[1]) : "r"(addr));
}
__device__ __forceinline__ void mma_bf16(float* c, const uint32_t* a, const uint32_t* b) {
    asm volatile("mma.sync.aligned.m16n8k16.row.col.f32.bf16.bf16.f32 "
        "{%0,%1,%2,%3},{%4,%5,%6,%7},{%8,%9},{%0,%1,%2,%3};"
        : "+f"(c[0]), "+f"(c[1]), "+f"(c[2]), "+f"(c[3])
        : "r"(a[0]), "r"(a[1]), "r"(a[2]), "r"(a[3]), "r"(b[0]), "r"(b[1]));
}

// ---- (1) fused copy + label extraction for one_hot, warp per row -------------
__global__ void copy_labels_k(const float* __restrict__ oh, float* __restrict__ dstcopy) {
    int row  = blockIdx.x * (blockDim.x >> 5) + (threadIdx.x >> 5);
    int lane = threadIdx.x & 31;
    if (row >= 2 * NL) return;
    const float* r = oh + (size_t)row * CC;
    float* d = dstcopy + (size_t)row * CC;
    int lab = -1;
    for (int c = lane; c < CC; c += 32) {
        float v = r[c];
        d[c] = v;
        if (v > 0.5f) lab = c;
    }
    #pragma unroll
    for (int o = 16; o; o >>= 1) lab = max(lab, __shfl_xor_sync(0xffffffffu, lab, o));
    if (lane == 0) g_labels[row] = lab;
}

// ---- (2) fused copy + l2-normalize -> bf16 for anchor & positive -------------
__global__ void copy_norm_q_k(const float* __restrict__ anchor, const float* __restrict__ pos,
                              float* __restrict__ dstA, float* __restrict__ dstP) {
    int row  = blockIdx.x * (blockDim.x >> 5) + (threadIdx.x >> 5);
    int lane = threadIdx.x & 31;
    int sel  = blockIdx.y;
    if (row >= NU) return;
    const float* src = (sel == 0) ? anchor : pos;
    float* dstcopy   = (sel == 0) ? dstA : dstP;
    __nv_bfloat16* nb = ((sel == 0) ? g_aqh : g_pqh) + (size_t)row * DD;
    const float4* s4 = (const float4*)(src + (size_t)row * DD);
    float4* d4 = (float4*)(dstcopy + (size_t)row * DD);
    float4 v[4];
    float acc = 0.f;
    #pragma unroll
    for (int i = 0; i < 4; i++) {
        v[i] = s4[lane + 32 * i];
        acc += v[i].x * v[i].x + v[i].y * v[i].y + v[i].z * v[i].z + v[i].w * v[i].w;
    }
    #pragma unroll
    for (int o = 16; o; o >>= 1) acc += __shfl_xor_sync(0xffffffffu, acc, o);
    float inv = 1.0f / fmaxf(sqrtf(acc), 1e-12f);
    #pragma unroll
    for (int i = 0; i < 4; i++) {
        d4[lane + 32 * i] = v[i];
        int c = (lane + 32 * i) * 4;
        nb[c + 0] = __float2bfloat16(v[i].x * inv);
        nb[c + 1] = __float2bfloat16(v[i].y * inv);
        nb[c + 2] = __float2bfloat16(v[i].z * inv);
        nb[c + 3] = __float2bfloat16(v[i].w * inv);
    }
}

// ---- (3) copy lb + copy lgx + zero ulb accumulators + zero rowsums -----------
// Segments (float4 units within the respective regions):
//   [0, NL4)            : lb -> out+oL
//   [NL4, NL4+NG4)      : lgx -> out+oLG
//   [.., +NZ4)          : zero out+oU1 (2*NU*CC floats)
//   tail                : zero g_rowsum
#define NL4 2097152u                 // 2*NL*DD/4
#define NG4 4096000u                 // 2*NL*CC/4
#define NZ4 4096000u                 // 2*NU*CC/4
#define NR4 4096u                    // 2*NU/4
#define NTOT4 (NL4 + NG4 + NZ4 + NR4)
__global__ void copy_rest_k(const float4* __restrict__ lb, const float4* __restrict__ lgx,
                            float4* __restrict__ outL, float4* __restrict__ outLG,
                            float4* __restrict__ outU) {
    uint32_t i = blockIdx.x * blockDim.x + threadIdx.x;
    if (i >= NTOT4) return;
    if (i < NL4) { outL[i] = lb[i]; return; }
    i -= NL4;
    if (i < NG4) { outLG[i] = lgx[i]; return; }
    i -= NG4;
    float4 z = make_float4(0.f, 0.f, 0.f, 0.f);
    if (i < NZ4) { outU[i] = z; return; }
    i -= NZ4;
    ((float4*)g_rowsum)[i] = z;
}

// ---- (4) single-CTA counting sort: counts + scan + scatter -------------------
__global__ void __launch_bounds__(1024) sort_k() {
    __shared__ int cnt[CC];
    __shared__ int cur[CC + 1];
    __shared__ int ws[32];
    int tid = threadIdx.x;
    int h   = blockIdx.x;
    for (int c = tid; c < CC; c += 1024) cnt[c] = 0;
    __syncthreads();
    const int* lab = g_labels + h * NL;
    for (int i = tid; i < NL; i += 1024) atomicAdd(&cnt[lab[i]], 1);
    __syncthreads();
    // exclusive scan over cnt[0..CC)
    int lane = tid & 31, wid = tid >> 5;
    int v = (tid < CC) ? cnt[tid] : 0;
    int x = v;
    #pragma unroll
    for (int o = 1; o < 32; o <<= 1) {
        int y = __shfl_up_sync(0xffffffffu, x, o);
        if (lane >= o) x += y;
    }
    if (lane == 31) ws[wid] = x;
    __syncthreads();
    if (wid == 0) {
        int s = ws[lane];
        #pragma unroll
        for (int o = 1; o < 32; o <<= 1) {
            int y = __shfl_up_sync(0xffffffffu, s, o);
            if (lane >= o) s += y;
        }
        ws[lane] = s;
    }
    __syncthreads();
    int excl = x - v + (wid > 0 ? ws[wid - 1] : 0);
    if (tid < CC) {
        g_offsets[h * (CC + 1) + tid] = excl;
        cur[tid] = excl;
    }
    if (tid == CC) g_offsets[h * (CC + 1) + CC] = excl;   // v=0 at tid==CC
    __syncthreads();
    int* perm = g_perm + h * NL;
    for (int i = tid; i < NL; i += 1024) {
        int pos = atomicAdd(&cur[lab[i]], 1);
        perm[pos] = i;
    }
}

// ---- (5) supports: normalize, write in class-sorted (perm) order -------------
__global__ void norm_sup_k(const float* __restrict__ lb) {
    int row  = blockIdx.x * (blockDim.x >> 5) + (threadIdx.x >> 5);
    int lane = threadIdx.x & 31;
    if (row >= 2 * NL) return;
    int half = row / NL;
    int pos  = row - half * NL;
    int srow = half * NL + g_perm[half * NL + pos];
    const float* s = lb + (size_t)srow * DD;
    float v[16];
    float acc = 0.f;
    #pragma unroll
    for (int i = 0; i < 16; i++) { v[i] = s[lane + 32 * i]; acc += v[i] * v[i]; }
    #pragma unroll
    for (int o = 16; o; o >>= 1) acc += __shfl_xor_sync(0xffffffffu, acc, o);
    float inv = 1.0f / fmaxf(sqrtf(acc), 1e-12f);
    __nv_bfloat16* d = g_suph + (size_t)row * DD;
    #pragma unroll
    for (int i = 0; i < 16; i++) d[lane + 32 * i] = __float2bfloat16(v[i] * inv);
}

// ---- (6) GEMM + exp + class partial-sum epilogue -----------------------------
#define BM 128
#define BN 128
#define BKK 32
#define STAGES 4
#define NKIT (DD / BKK)                 // 16
#define SROW 80
#define TILE_BYTES (BM * SROW)          // 10240
#define STAGE_BYTES (2 * TILE_BYTES)    // 20480
#define EP_PITCH 129
#define C2C_OFF (STAGES * STAGE_BYTES)  // 81920
#define GEMM_SMEM (C2C_OFF + 512)       // 82432

__global__ void __launch_bounds__(256, 2) gemm_fused_k(float* __restrict__ ulbbase) {
    extern __shared__ __align__(16) char smem[];
    const uint32_t sbase = smem_u32(smem);

    const int tid  = threadIdx.x;
    const int wid  = tid >> 5;
    const int lane = tid & 31;
    const int wr   = wid & 1;
    const int wc   = wid >> 1;

    const int z  = blockIdx.z;
    const __nv_bfloat16* A = (z == 0) ? g_aqh : g_pqh;
    const __nv_bfloat16* B = g_suph + (size_t)z * NL * DD;
    const int m0 = blockIdx.y * BM;
    const int n0 = blockIdx.x * BN;
    const __nv_bfloat16* Abase = A + (size_t)m0 * DD;
    const __nv_bfloat16* Bbase = B + (size_t)n0 * DD;

    const int r0 = tid >> 2, r1 = r0 + 64;
    const int c0 = (tid & 3) * 8;

    float acc[4][4][4];
    #pragma unroll
    for (int mi = 0; mi < 4; mi++)
        #pragma unroll
        for (int ni = 0; ni < 4; ni++)
            #pragma unroll
            for (int q = 0; q < 4; q++) acc[mi][ni][q] = 0.f;

    #pragma unroll
    for (int s = 0; s < STAGES - 1; s++) {
        uint32_t sA = sbase + s * STAGE_BYTES;
        uint32_t sB = sA + TILE_BYTES;
        const __nv_bfloat16* Ak = Abase + s * BKK;
        const __nv_bfloat16* Bk = Bbase + s * BKK;
        CP_ASYNC16(sA + r0 * SROW + c0 * 2, Ak + (size_t)r0 * DD + c0);
        CP_ASYNC16(sA + r1 * SROW + c0 * 2, Ak + (size_t)r1 * DD + c0);
        CP_ASYNC16(sB + r0 * SROW + c0 * 2, Bk + (size_t)r0 * DD + c0);
        CP_ASYNC16(sB + r1 * SROW + c0 * 2, Bk + (size_t)r1 * DD + c0);
        CP_COMMIT();
    }

    const uint32_t aOff = (uint32_t)(wr * 64 + (lane & 15)) * SROW + (lane >> 4) * 16;
    const uint32_t bOff = (uint32_t)(wc * 32 + (lane & 7)) * SROW + ((lane >> 3) & 1) * 16;

    for (int kc = 0; kc < NKIT; kc++) {
        const int st = kc % STAGES;
        CP_WAIT(STAGES - 2);
        __syncthreads();

        const int pf = kc + STAGES - 1;
        if (pf < NKIT) {
            const int ps = pf % STAGES;
            uint32_t sA = sbase + ps * STAGE_BYTES;
            uint32_t sB = sA + TILE_BYTES;
            const __nv_bfloat16* Ak = Abase + pf * BKK;
            const __nv_bfloat16* Bk = Bbase + pf * BKK;
            CP_ASYNC16(sA + r0 * SROW + c0 * 2, Ak + (size_t)r0 * DD + c0);
            CP_ASYNC16(sA + r1 * SROW + c0 * 2, Ak + (size_t)r1 * DD + c0);
            CP_ASYNC16(sB + r0 * SROW + c0 * 2, Bk + (size_t)r0 * DD + c0);
            CP_ASYNC16(sB + r1 * SROW + c0 * 2, Bk + (size_t)r1 * DD + c0);
        }
        CP_COMMIT();

        const uint32_t sA = sbase + st * STAGE_BYTES;
        const uint32_t sB = sA + TILE_BYTES;
        #pragma unroll
        for (int kk = 0; kk < 2; kk++) {
            uint32_t aF[4][4], bF[4][2];
            #pragma unroll
            for (int mi = 0; mi < 4; mi++)
                ldsm_x4(aF[mi], sA + aOff + (uint32_t)mi * 16 * SROW + kk * 32);
            #pragma unroll
            for (int ni = 0; ni < 4; ni++)
                ldsm_x2(bF[ni], sB + bOff + (uint32_t)ni * 8 * SROW + kk * 32);
            #pragma unroll
            for (int mi = 0; mi < 4; mi++)
                #pragma unroll
                for (int ni = 0; ni < 4; ni++)
                    mma_bf16(acc[mi][ni], aF[mi], bF[ni]);
        }
    }

    // ---- epilogue: exp -> smem, per-row contiguous segment sums, atomics ----
    CP_WAIT(0);
    __syncthreads();

    float* ep    = (float*)smem;
    int*   c2c_s = (int*)(smem + C2C_OFF);

    const int ebr = wr * 64 + (lane >> 2);
    const int ebc = wc * 32 + (lane & 3) * 2;
    #pragma unroll
    for (int mi = 0; mi < 4; mi++) {
        #pragma unroll
        for (int ni = 0; ni < 4; ni++) {
            int rr = ebr + mi * 16, cc2 = ebc + ni * 8;
            ep[rr * EP_PITCH + cc2]           = __expf(acc[mi][ni][0] * INV_TAU);
            ep[rr * EP_PITCH + cc2 + 1]       = __expf(acc[mi][ni][1] * INV_TAU);
            ep[(rr + 8) * EP_PITCH + cc2]     = __expf(acc[mi][ni][2] * INV_TAU);
            ep[(rr + 8) * EP_PITCH + cc2 + 1] = __expf(acc[mi][ni][3] * INV_TAU);
        }
    }
    if (tid < BN) {
        const int* offs = g_offsets + z * (CC + 1);
        int v = n0 + tid;
        int lo = 0, hi = CC - 1;
        while (lo < hi) { int mid = (lo + hi + 1) >> 1; if (offs[mid] <= v) lo = mid; else hi = mid - 1; }
        c2c_s[tid] = lo;
    }
    __syncthreads();

    if (tid < BM) {
        float* orow = ulbbase + (size_t)z * NU * CC + (size_t)(m0 + tid) * CC;
        const float* er = ep + tid * EP_PITCH;
        float run = 0.f, rs = 0.f;
        int cls = c2c_s[0];
        #pragma unroll 4
        for (int j = 0; j < BN; j++) {
            int c2 = c2c_s[j];
            float e = er[j];
            if (c2 != cls) { atomicAdd(&orow[cls], run); run = 0.f; cls = c2; }
            run += e;
            rs  += e;
        }
        atomicAdd(&orow[cls], run);
        atomicAdd(&g_rowsum[z * NU + m0 + tid], rs);
    }
}

// ---- (7) normalize + zero empty classes --------------------------------------
__global__ void __launch_bounds__(256) normalize_k(float* __restrict__ ulbbase) {
    int u = blockIdx.x;
    int z = blockIdx.y;
    float inv = 1.0f / g_rowsum[z * NU + u];
    const int* offs = g_offsets + z * (CC + 1);
    float* orow = ulbbase + (size_t)z * NU * CC + (size_t)u * CC;
    for (int c = threadIdx.x; c < CC; c += 256) {
        float v = orow[c];
        orow[c] = (offs[c + 1] > offs[c]) ? v * inv : 0.f;
    }
}

// ---------------- launch ------------------------------------------------------
extern "C" void kernel_launch(void* const* d_in, const int* in_sizes, int n_in,
                              void* d_out, int out_size) {
    const float* anchor = (const float*)d_in[0];
    const float* pos    = (const float*)d_in[1];
    const float* lb     = (const float*)d_in[2];
    const float* oh     = (const float*)d_in[3];
    const float* lgx    = (const float*)d_in[4];
    float* out = (float*)d_out;

    const size_t nA  = (size_t)NU * DD;
    const size_t nP  = (size_t)NU * DD;
    const size_t nL  = (size_t)2 * NL * DD;
    const size_t nOH = (size_t)2 * NL * CC;
    const size_t nLG = (size_t)2 * NL * CC;
    size_t oA  = 0;
    size_t oP  = oA + nA;
    size_t oL  = oP + nP;
    size_t oOH = oL + nL;
    size_t oLG = oOH + nOH;
    size_t oU1 = oLG + nLG;

    // (1) one_hot copy + label extraction
    copy_labels_k<<<(2 * NL) / 8, 256>>>(oh, out + oOH);
    // (2) anchor+positive copy + normalize
    dim3 gq(NU / 8, 2);
    copy_norm_q_k<<<gq, 256>>>(anchor, pos, out + oA, out + oP);
    // (3) lb copy + lgx copy + zero ulb + zero rowsums
    copy_rest_k<<<(NTOT4 + 255) / 256, 256>>>(
        (const float4*)lb, (const float4*)lgx,
        (float4*)(out + oL), (float4*)(out + oLG), (float4*)(out + oU1));
    // (4) counting sort, one CTA per half
    sort_k<<<2, 1024>>>();
    // (5) supports: normalize in class-sorted order
    norm_sup_k<<<(2 * NL) / 8, 256>>>(lb);
    // (6) GEMM with fused exp + class partial-sum epilogue
    cudaFuncSetAttribute(gemm_fused_k, cudaFuncAttributeMaxDynamicSharedMemorySize, GEMM_SMEM);
    dim3 gg(NL / BN, NU / BM, 2);
    gemm_fused_k<<<gg, 256, GEMM_SMEM>>>(out + oU1);
    // (7) normalize + zero empty classes
    dim3 gn(NU, 2);
    normalize_k<<<gn, 256>>>(out + oU1);
}

// round 13
// speedup vs baseline: 1.4014x; 1.4014x over previous
#include <cuda_runtime.h>
#include <cuda_bf16.h>
#include <math_constants.h>
#include <cstdint>

// Problem constants
#define NU   8192
#define NL   8192     // per half
#define DD   512
#define CC   1000
#define INV_TAU 10.0f

// ---------------- device scratch ---------------------------------------------
__device__ __nv_bfloat16 g_aqh [NU * DD];
__device__ __nv_bfloat16 g_pqh [NU * DD];
__device__ __nv_bfloat16 g_suph[2 * NL * DD];     // class-sorted order
__device__ float g_rowsum[2 * NU];
__device__ int   g_labels[2 * NL];
__device__ int   g_offsets[2 * (CC + 1)];
__device__ int   g_perm[2 * NL];

// ---------------- PTX helpers -------------------------------------------------
__device__ __forceinline__ uint32_t smem_u32(const void* p) {
    uint32_t a;
    asm("{ .reg .u64 t; cvta.to.shared.u64 t, %1; cvt.u32.u64 %0, t; }" : "=r"(a) : "l"(p));
    return a;
}
#define CP_ASYNC16(s, g) asm volatile("cp.async.cg.shared.global [%0], [%1], 16;" :: "r"(s), "l"(g))
#define CP_COMMIT()      asm volatile("cp.async.commit_group;" ::: "memory")
#define CP_WAIT(n)       asm volatile("cp.async.wait_group %0;" :: "n"(n) : "memory")

__device__ __forceinline__ void ldsm_x4(uint32_t* r, uint32_t addr) {
    asm volatile("ldmatrix.sync.aligned.m8n8.x4.shared.b16 {%0,%1,%2,%3}, [%4];"
        : "=r"(r[0]), "=r"(r[1]), "=r"(r[2]), "=r"(r[3]) : "r"(addr));
}
__device__ __forceinline__ void ldsm_x2(uint32_t* r, uint32_t addr) {
    asm volatile("ldmatrix.sync.aligned.m8n8.x2.shared.b16 {%0,%1}, [%2];"
        : "=r"(r[0]), "=r"(r[1]) : "r"(addr));
}
__device__ __forceinline__ void mma_bf16(float* c, const uint32_t* a, const uint32_t* b) {
    asm volatile("mma.sync.aligned.m16n8k16.row.col.f32.bf16.bf16.f32 "
        "{%0,%1,%2,%3},{%4,%5,%6,%7},{%8,%9},{%0,%1,%2,%3};"
        : "+f"(c[0]), "+f"(c[1]), "+f"(c[2]), "+f"(c[3])
        : "r"(a[0]), "r"(a[1]), "r"(a[2]), "r"(a[3]), "r"(b[0]), "r"(b[1]));
}

// ---- (1) fused copy + label extraction for one_hot, warp per row -------------
__global__ void copy_labels_k(const float* __restrict__ oh, float* __restrict__ dstcopy) {
    int row  = blockIdx.x * (blockDim.x >> 5) + (threadIdx.x >> 5);
    int lane = threadIdx.x & 31;
    if (row >= 2 * NL) return;
    const float* r = oh + (size_t)row * CC;
    float* d = dstcopy + (size_t)row * CC;
    int lab = -1;
    for (int c = lane; c < CC; c += 32) {
        float v = r[c];
        d[c] = v;
        if (v > 0.5f) lab = c;
    }
    #pragma unroll
    for (int o = 16; o; o >>= 1) lab = max(lab, __shfl_xor_sync(0xffffffffu, lab, o));
    if (lane == 0) g_labels[row] = lab;
}

// ---- (2) fused copy + l2-normalize -> bf16 for anchor & positive -------------
__global__ void copy_norm_q_k(const float* __restrict__ anchor, const float* __restrict__ pos,
                              float* __restrict__ dstA, float* __restrict__ dstP) {
    int row  = blockIdx.x * (blockDim.x >> 5) + (threadIdx.x >> 5);
    int lane = threadIdx.x & 31;
    int sel  = blockIdx.y;
    if (row >= NU) return;
    const float* src = (sel == 0) ? anchor : pos;
    float* dstcopy   = (sel == 0) ? dstA : dstP;
    __nv_bfloat16* nb = ((sel == 0) ? g_aqh : g_pqh) + (size_t)row * DD;
    const float4* s4 = (const float4*)(src + (size_t)row * DD);
    float4* d4 = (float4*)(dstcopy + (size_t)row * DD);
    float4 v[4];
    float acc = 0.f;
    #pragma unroll
    for (int i = 0; i < 4; i++) {
        v[i] = s4[lane + 32 * i];
        acc += v[i].x * v[i].x + v[i].y * v[i].y + v[i].z * v[i].z + v[i].w * v[i].w;
    }
    #pragma unroll
    for (int o = 16; o; o >>= 1) acc += __shfl_xor_sync(0xffffffffu, acc, o);
    float inv = 1.0f / fmaxf(sqrtf(acc), 1e-12f);
    #pragma unroll
    for (int i = 0; i < 4; i++) {
        d4[lane + 32 * i] = v[i];
        int c = (lane + 32 * i) * 4;
        nb[c + 0] = __float2bfloat16(v[i].x * inv);
        nb[c + 1] = __float2bfloat16(v[i].y * inv);
        nb[c + 2] = __float2bfloat16(v[i].z * inv);
        nb[c + 3] = __float2bfloat16(v[i].w * inv);
    }
}

// ---- (3) copy lb + copy lgx + zero ulb accumulators + zero rowsums -----------
#define NL4 2097152u                 // 2*NL*DD/4
#define NG4 4096000u                 // 2*NL*CC/4
#define NZ4 4096000u                 // 2*NU*CC/4
#define NR4 4096u                    // 2*NU/4
#define NTOT4 (NL4 + NG4 + NZ4 + NR4)
__global__ void copy_rest_k(const float4* __restrict__ lb, const float4* __restrict__ lgx,
                            float4* __restrict__ outL, float4* __restrict__ outLG,
                            float4* __restrict__ outU) {
    uint32_t i = blockIdx.x * blockDim.x + threadIdx.x;
    if (i >= NTOT4) return;
    if (i < NL4) { outL[i] = lb[i]; return; }
    i -= NL4;
    if (i < NG4) { outLG[i] = lgx[i]; return; }
    i -= NG4;
    float4 z = make_float4(0.f, 0.f, 0.f, 0.f);
    if (i < NZ4) { outU[i] = z; return; }
    i -= NZ4;
    ((float4*)g_rowsum)[i] = z;
}

// ---- (4) single-CTA counting sort: counts + scan + scatter -------------------
__global__ void __launch_bounds__(1024) sort_k() {
    __shared__ int cnt[CC];
    __shared__ int cur[CC + 1];
    __shared__ int ws[32];
    int tid = threadIdx.x;
    int h   = blockIdx.x;
    for (int c = tid; c < CC; c += 1024) cnt[c] = 0;
    __syncthreads();
    const int* lab = g_labels + h * NL;
    for (int i = tid; i < NL; i += 1024) atomicAdd(&cnt[lab[i]], 1);
    __syncthreads();
    int lane = tid & 31, wid = tid >> 5;
    int v = (tid < CC) ? cnt[tid] : 0;
    int x = v;
    #pragma unroll
    for (int o = 1; o < 32; o <<= 1) {
        int y = __shfl_up_sync(0xffffffffu, x, o);
        if (lane >= o) x += y;
    }
    if (lane == 31) ws[wid] = x;
    __syncthreads();
    if (wid == 0) {
        int s = ws[lane];
        #pragma unroll
        for (int o = 1; o < 32; o <<= 1) {
            int y = __shfl_up_sync(0xffffffffu, s, o);
            if (lane >= o) s += y;
        }
        ws[lane] = s;
    }
    __syncthreads();
    int excl = x - v + (wid > 0 ? ws[wid - 1] : 0);
    if (tid < CC) {
        g_offsets[h * (CC + 1) + tid] = excl;
        cur[tid] = excl;
    }
    if (tid == CC) g_offsets[h * (CC + 1) + CC] = excl;
    __syncthreads();
    int* perm = g_perm + h * NL;
    for (int i = tid; i < NL; i += 1024) {
        int pos = atomicAdd(&cur[lab[i]], 1);
        perm[pos] = i;
    }
}

// ---- (5) supports: normalize, write in class-sorted (perm) order -------------
__global__ void norm_sup_k(const float* __restrict__ lb) {
    int row  = blockIdx.x * (blockDim.x >> 5) + (threadIdx.x >> 5);
    int lane = threadIdx.x & 31;
    if (row >= 2 * NL) return;
    int half = row / NL;
    int pos  = row - half * NL;
    int srow = half * NL + g_perm[half * NL + pos];
    const float* s = lb + (size_t)srow * DD;
    float v[16];
    float acc = 0.f;
    #pragma unroll
    for (int i = 0; i < 16; i++) { v[i] = s[lane + 32 * i]; acc += v[i] * v[i]; }
    #pragma unroll
    for (int o = 16; o; o >>= 1) acc += __shfl_xor_sync(0xffffffffu, acc, o);
    float inv = 1.0f / fmaxf(sqrtf(acc), 1e-12f);
    __nv_bfloat16* d = g_suph + (size_t)row * DD;
    #pragma unroll
    for (int i = 0; i < 16; i++) d[lane + 32 * i] = __float2bfloat16(v[i] * inv);
}

// ---- (6) GEMM + exp + class partial-sum epilogue -----------------------------
#define BM 128
#define BN 128
#define BKK 32
#define STAGES 4
#define NKIT (DD / BKK)                 // 16
#define SROW 80
#define TILE_BYTES (BM * SROW)          // 10240
#define STAGE_BYTES (2 * TILE_BYTES)    // 20480
#define EP_PITCH 129
#define C2C_OFF (STAGES * STAGE_BYTES)  // 81920
#define GEMM_SMEM (C2C_OFF + 512)       // 82432

__global__ void __launch_bounds__(256) gemm_fused_k(float* __restrict__ ulbbase) {
    extern __shared__ __align__(16) char smem[];
    const uint32_t sbase = smem_u32(smem);

    const int tid  = threadIdx.x;
    const int wid  = tid >> 5;
    const int lane = tid & 31;
    const int wr   = wid & 1;
    const int wc   = wid >> 1;

    const int z  = blockIdx.z;
    const __nv_bfloat16* A = (z == 0) ? g_aqh : g_pqh;
    const __nv_bfloat16* B = g_suph + (size_t)z * NL * DD;
    const int m0 = blockIdx.y * BM;
    const int n0 = blockIdx.x * BN;
    const __nv_bfloat16* Abase = A + (size_t)m0 * DD;
    const __nv_bfloat16* Bbase = B + (size_t)n0 * DD;

    const int r0 = tid >> 2, r1 = r0 + 64;
    const int c0 = (tid & 3) * 8;

    float acc[4][4][4];
    #pragma unroll
    for (int mi = 0; mi < 4; mi++)
        #pragma unroll
        for (int ni = 0; ni < 4; ni++)
            #pragma unroll
            for (int q = 0; q < 4; q++) acc[mi][ni][q] = 0.f;

    #pragma unroll
    for (int s = 0; s < STAGES - 1; s++) {
        uint32_t sA = sbase + s * STAGE_BYTES;
        uint32_t sB = sA + TILE_BYTES;
        const __nv_bfloat16* Ak = Abase + s * BKK;
        const __nv_bfloat16* Bk = Bbase + s * BKK;
        CP_ASYNC16(sA + r0 * SROW + c0 * 2, Ak + (size_t)r0 * DD + c0);
        CP_ASYNC16(sA + r1 * SROW + c0 * 2, Ak + (size_t)r1 * DD + c0);
        CP_ASYNC16(sB + r0 * SROW + c0 * 2, Bk + (size_t)r0 * DD + c0);
        CP_ASYNC16(sB + r1 * SROW + c0 * 2, Bk + (size_t)r1 * DD + c0);
        CP_COMMIT();
    }

    const uint32_t aOff = (uint32_t)(wr * 64 + (lane & 15)) * SROW + (lane >> 4) * 16;
    const uint32_t bOff = (uint32_t)(wc * 32 + (lane & 7)) * SROW + ((lane >> 3) & 1) * 16;

    for (int kc = 0; kc < NKIT; kc++) {
        const int st = kc % STAGES;
        CP_WAIT(STAGES - 2);
        __syncthreads();

        const int pf = kc + STAGES - 1;
        if (pf < NKIT) {
            const int ps = pf % STAGES;
            uint32_t sA = sbase + ps * STAGE_BYTES;
            uint32_t sB = sA + TILE_BYTES;
            const __nv_bfloat16* Ak = Abase + pf * BKK;
            const __nv_bfloat16* Bk = Bbase + pf * BKK;
            CP_ASYNC16(sA + r0 * SROW + c0 * 2, Ak + (size_t)r0 * DD + c0);
            CP_ASYNC16(sA + r1 * SROW + c0 * 2, Ak + (size_t)r1 * DD + c0);
            CP_ASYNC16(sB + r0 * SROW + c0 * 2, Bk + (size_t)r0 * DD + c0);
            CP_ASYNC16(sB + r1 * SROW + c0 * 2, Bk + (size_t)r1 * DD + c0);
        }
        CP_COMMIT();

        const uint32_t sA = sbase + st * STAGE_BYTES;
        const uint32_t sB = sA + TILE_BYTES;
        #pragma unroll
        for (int kk = 0; kk < 2; kk++) {
            uint32_t aF[4][4], bF[4][2];
            #pragma unroll
            for (int mi = 0; mi < 4; mi++)
                ldsm_x4(aF[mi], sA + aOff + (uint32_t)mi * 16 * SROW + kk * 32);
            #pragma unroll
            for (int ni = 0; ni < 4; ni++)
                ldsm_x2(bF[ni], sB + bOff + (uint32_t)ni * 8 * SROW + kk * 32);
            #pragma unroll
            for (int mi = 0; mi < 4; mi++)
                #pragma unroll
                for (int ni = 0; ni < 4; ni++)
                    mma_bf16(acc[mi][ni], aF[mi], bF[ni]);
        }
    }

    // ---- epilogue: exp -> smem, per-row contiguous segment sums, atomics ----
    CP_WAIT(0);
    __syncthreads();

    float* ep    = (float*)smem;
    int*   c2c_s = (int*)(smem + C2C_OFF);

    const int ebr = wr * 64 + (lane >> 2);
    const int ebc = wc * 32 + (lane & 3) * 2;
    #pragma unroll
    for (int mi = 0; mi < 4; mi++) {
        #pragma unroll
        for (int ni = 0; ni < 4; ni++) {
            int rr = ebr + mi * 16, cc2 = ebc + ni * 8;
            ep[rr * EP_PITCH + cc2]           = __expf(acc[mi][ni][0] * INV_TAU);
            ep[rr * EP_PITCH + cc2 + 1]       = __expf(acc[mi][ni][1] * INV_TAU);
            ep[(rr + 8) * EP_PITCH + cc2]     = __expf(acc[mi][ni][2] * INV_TAU);
            ep[(rr + 8) * EP_PITCH + cc2 + 1] = __expf(acc[mi][ni][3] * INV_TAU);
        }
    }
    if (tid < BN) {
        const int* offs = g_offsets + z * (CC + 1);
        int v = n0 + tid;
        int lo = 0, hi = CC - 1;
        while (lo < hi) { int mid = (lo + hi + 1) >> 1; if (offs[mid] <= v) lo = mid; else hi = mid - 1; }
        c2c_s[tid] = lo;
    }
    __syncthreads();

    if (tid < BM) {
        float* orow = ulbbase + (size_t)z * NU * CC + (size_t)(m0 + tid) * CC;
        const float* er = ep + tid * EP_PITCH;
        float run = 0.f, rs = 0.f;
        int cls = c2c_s[0];
        #pragma unroll 4
        for (int j = 0; j < BN; j++) {
            int c2 = c2c_s[j];
            float e = er[j];
            if (c2 != cls) { atomicAdd(&orow[cls], run); run = 0.f; cls = c2; }
            run += e;
            rs  += e;
        }
        atomicAdd(&orow[cls], run);
        atomicAdd(&g_rowsum[z * NU + m0 + tid], rs);
    }
}

// ---- (7) normalize + zero empty classes --------------------------------------
__global__ void __launch_bounds__(256) normalize_k(float* __restrict__ ulbbase) {
    int u = blockIdx.x;
    int z = blockIdx.y;
    float inv = 1.0f / g_rowsum[z * NU + u];
    const int* offs = g_offsets + z * (CC + 1);
    float* orow = ulbbase + (size_t)z * NU * CC + (size_t)u * CC;
    for (int c = threadIdx.x; c < CC; c += 256) {
        float v = orow[c];
        orow[c] = (offs[c + 1] > offs[c]) ? v * inv : 0.f;
    }
}

// ---------------- launch ------------------------------------------------------
extern "C" void kernel_launch(void* const* d_in, const int* in_sizes, int n_in,
                              void* d_out, int out_size) {
    const float* anchor = (const float*)d_in[0];
    const float* pos    = (const float*)d_in[1];
    const float* lb     = (const float*)d_in[2];
    const float* oh     = (const float*)d_in[3];
    const float* lgx    = (const float*)d_in[4];
    float* out = (float*)d_out;

    const size_t nA  = (size_t)NU * DD;
    const size_t nP  = (size_t)NU * DD;
    const size_t nL  = (size_t)2 * NL * DD;
    const size_t nOH = (size_t)2 * NL * CC;
    const size_t nLG = (size_t)2 * NL * CC;
    size_t oA  = 0;
    size_t oP  = oA + nA;
    size_t oL  = oP + nP;
    size_t oOH = oL + nL;
    size_t oLG = oOH + nOH;
    size_t oU1 = oLG + nLG;

    // (1) one_hot copy + label extraction
    copy_labels_k<<<(2 * NL) / 8, 256>>>(oh, out + oOH);
    // (2) anchor+positive copy + normalize
    dim3 gq(NU / 8, 2);
    copy_norm_q_k<<<gq, 256>>>(anchor, pos, out + oA, out + oP);
    // (3) lb copy + lgx copy + zero ulb + zero rowsums
    copy_rest_k<<<(NTOT4 + 255) / 256, 256>>>(
        (const float4*)lb, (const float4*)lgx,
        (float4*)(out + oL), (float4*)(out + oLG), (float4*)(out + oU1));
    // (4) counting sort, one CTA per half
    sort_k<<<2, 1024>>>();
    // (5) supports: normalize in class-sorted order
    norm_sup_k<<<(2 * NL) / 8, 256>>>(lb);
    // (6) GEMM with fused exp + class partial-sum epilogue
    cudaFuncSetAttribute(gemm_fused_k, cudaFuncAttributeMaxDynamicSharedMemorySize, GEMM_SMEM);
    dim3 gg(NL / BN, NU / BM, 2);
    gemm_fused_k<<<gg, 256, GEMM_SMEM>>>(out + oU1);
    // (7) normalize + zero empty classes
    dim3 gn(NU, 2);
    normalize_k<<<gn, 256>>>(out + oU1);
}

// round 14
// speedup vs baseline: 1.4188x; 1.0125x over previous
#include <cuda_runtime.h>
#include <cuda_bf16.h>
#include <math_constants.h>
#include <cstdint>

// Problem constants
#define NU   8192
#define NL   8192     // per half
#define DD   512
#define CC   1000
#define INV_TAU 10.0f

// ---------------- device scratch ---------------------------------------------
__device__ __nv_bfloat16 g_aqh [NU * DD];
__device__ __nv_bfloat16 g_pqh [NU * DD];
__device__ __nv_bfloat16 g_suph[2 * NL * DD];     // class-sorted order
__device__ float g_rowsum[2 * NU];
__device__ int   g_labels[2 * NL];
__device__ int   g_offsets[2 * (CC + 1)];
__device__ int   g_perm[2 * NL];

// ---------------- PTX helpers -------------------------------------------------
__device__ __forceinline__ uint32_t smem_u32(const void* p) {
    uint32_t a;
    asm("{ .reg .u64 t; cvta.to.shared.u64 t, %1; cvt.u32.u64 %0, t; }" : "=r"(a) : "l"(p));
    return a;
}
#define CP_ASYNC16(s, g) asm volatile("cp.async.cg.shared.global [%0], [%1], 16;" :: "r"(s), "l"(g))
#define CP_COMMIT()      asm volatile("cp.async.commit_group;" ::: "memory")
#define CP_WAIT(n)       asm volatile("cp.async.wait_group %0;" :: "n"(n) : "memory")

__device__ __forceinline__ void ldsm_x4(uint32_t* r, uint32_t addr) {
    asm volatile("ldmatrix.sync.aligned.m8n8.x4.shared.b16 {%0,%1,%2,%3}, [%4];"
        : "=r"(r[0]), "=r"(r[1]), "=r"(r[2]), "=r"(r[3]) : "r"(addr));
}
__device__ __forceinline__ void ldsm_x2(uint32_t* r, uint32_t addr) {
    asm volatile("ldmatrix.sync.aligned.m8n8.x2.shared.b16 {%0,%1}, [%2];"
        : "=r"(r[0]), "=r"(r[1]) : "r"(addr));
}
__device__ __forceinline__ void mma_bf16(float* c, const uint32_t* a, const uint32_t* b) {
    asm volatile("mma.sync.aligned.m16n8k16.row.col.f32.bf16.bf16.f32 "
        "{%0,%1,%2,%3},{%4,%5,%6,%7},{%8,%9},{%0,%1,%2,%3};"
        : "+f"(c[0]), "+f"(c[1]), "+f"(c[2]), "+f"(c[3])
        : "r"(a[0]), "r"(a[1]), "r"(a[2]), "r"(a[3]), "r"(b[0]), "r"(b[1]));
}

// ---- (1) fused copy + label extraction for one_hot, warp per row -------------
__global__ void copy_labels_k(const float* __restrict__ oh, float* __restrict__ dstcopy) {
    int row  = blockIdx.x * (blockDim.x >> 5) + (threadIdx.x >> 5);
    int lane = threadIdx.x & 31;
    if (row >= 2 * NL) return;
    const float* r = oh + (size_t)row * CC;
    float* d = dstcopy + (size_t)row * CC;
    int lab = -1;
    for (int c = lane; c < CC; c += 32) {
        float v = r[c];
        d[c] = v;
        if (v > 0.5f) lab = c;
    }
    #pragma unroll
    for (int o = 16; o; o >>= 1) lab = max(lab, __shfl_xor_sync(0xffffffffu, lab, o));
    if (lane == 0) g_labels[row] = lab;
}

// ---- (2) fused copy + l2-normalize -> bf16 for anchor & positive -------------
__global__ void copy_norm_q_k(const float* __restrict__ anchor, const float* __restrict__ pos,
                              float* __restrict__ dstA, float* __restrict__ dstP) {
    int row  = blockIdx.x * (blockDim.x >> 5) + (threadIdx.x >> 5);
    int lane = threadIdx.x & 31;
    int sel  = blockIdx.y;
    if (row >= NU) return;
    const float* src = (sel == 0) ? anchor : pos;
    float* dstcopy   = (sel == 0) ? dstA : dstP;
    __nv_bfloat16* nb = ((sel == 0) ? g_aqh : g_pqh) + (size_t)row * DD;
    const float4* s4 = (const float4*)(src + (size_t)row * DD);
    float4* d4 = (float4*)(dstcopy + (size_t)row * DD);
    float4 v[4];
    float acc = 0.f;
    #pragma unroll
    for (int i = 0; i < 4; i++) {
        v[i] = s4[lane + 32 * i];
        acc += v[i].x * v[i].x + v[i].y * v[i].y + v[i].z * v[i].z + v[i].w * v[i].w;
    }
    #pragma unroll
    for (int o = 16; o; o >>= 1) acc += __shfl_xor_sync(0xffffffffu, acc, o);
    float inv = 1.0f / fmaxf(sqrtf(acc), 1e-12f);
    #pragma unroll
    for (int i = 0; i < 4; i++) {
        d4[lane + 32 * i] = v[i];
        int c = (lane + 32 * i) * 4;
        nb[c + 0] = __float2bfloat16(v[i].x * inv);
        nb[c + 1] = __float2bfloat16(v[i].y * inv);
        nb[c + 2] = __float2bfloat16(v[i].z * inv);
        nb[c + 3] = __float2bfloat16(v[i].w * inv);
    }
}

// ---- (3) copy lb + copy lgx + zero ulb accumulators + zero rowsums -----------
#define NL4 2097152u
#define NG4 4096000u
#define NZ4 4096000u
#define NR4 4096u
#define NTOT4 (NL4 + NG4 + NZ4 + NR4)
__global__ void copy_rest_k(const float4* __restrict__ lb, const float4* __restrict__ lgx,
                            float4* __restrict__ outL, float4* __restrict__ outLG,
                            float4* __restrict__ outU) {
    uint32_t i = blockIdx.x * blockDim.x + threadIdx.x;
    if (i >= NTOT4) return;
    if (i < NL4) { outL[i] = lb[i]; return; }
    i -= NL4;
    if (i < NG4) { outLG[i] = lgx[i]; return; }
    i -= NG4;
    float4 z = make_float4(0.f, 0.f, 0.f, 0.f);
    if (i < NZ4) { outU[i] = z; return; }
    i -= NZ4;
    ((float4*)g_rowsum)[i] = z;
}

// ---- (4) single-CTA counting sort: counts + scan + scatter -------------------
__global__ void __launch_bounds__(1024) sort_k() {
    __shared__ int cnt[CC];
    __shared__ int cur[CC + 1];
    __shared__ int ws[32];
    int tid = threadIdx.x;
    int h   = blockIdx.x;
    for (int c = tid; c < CC; c += 1024) cnt[c] = 0;
    __syncthreads();
    const int* lab = g_labels + h * NL;
    for (int i = tid; i < NL; i += 1024) atomicAdd(&cnt[lab[i]], 1);
    __syncthreads();
    int lane = tid & 31, wid = tid >> 5;
    int v = (tid < CC) ? cnt[tid] : 0;
    int x = v;
    #pragma unroll
    for (int o = 1; o < 32; o <<= 1) {
        int y = __shfl_up_sync(0xffffffffu, x, o);
        if (lane >= o) x += y;
    }
    if (lane == 31) ws[wid] = x;
    __syncthreads();
    if (wid == 0) {
        int s = ws[lane];
        #pragma unroll
        for (int o = 1; o < 32; o <<= 1) {
            int y = __shfl_up_sync(0xffffffffu, s, o);
            if (lane >= o) s += y;
        }
        ws[lane] = s;
    }
    __syncthreads();
    int excl = x - v + (wid > 0 ? ws[wid - 1] : 0);
    if (tid < CC) {
        g_offsets[h * (CC + 1) + tid] = excl;
        cur[tid] = excl;
    }
    if (tid == CC) g_offsets[h * (CC + 1) + CC] = excl;
    __syncthreads();
    int* perm = g_perm + h * NL;
    for (int i = tid; i < NL; i += 1024) {
        int pos = atomicAdd(&cur[lab[i]], 1);
        perm[pos] = i;
    }
}

// ---- (5) supports: normalize, write in class-sorted (perm) order -------------
__global__ void norm_sup_k(const float* __restrict__ lb) {
    int row  = blockIdx.x * (blockDim.x >> 5) + (threadIdx.x >> 5);
    int lane = threadIdx.x & 31;
    if (row >= 2 * NL) return;
    int half = row / NL;
    int pos  = row - half * NL;
    int srow = half * NL + g_perm[half * NL + pos];
    const float* s = lb + (size_t)srow * DD;
    float v[16];
    float acc = 0.f;
    #pragma unroll
    for (int i = 0; i < 16; i++) { v[i] = s[lane + 32 * i]; acc += v[i] * v[i]; }
    #pragma unroll
    for (int o = 16; o; o >>= 1) acc += __shfl_xor_sync(0xffffffffu, acc, o);
    float inv = 1.0f / fmaxf(sqrtf(acc), 1e-12f);
    __nv_bfloat16* d = g_suph + (size_t)row * DD;
    #pragma unroll
    for (int i = 0; i < 16; i++) d[lane + 32 * i] = __float2bfloat16(v[i] * inv);
}

// ---- (6) GEMM + exp + class partial-sum epilogue, 512 threads / 16 warps -----
#define BM 128
#define BN 128
#define BKK 32
#define STAGES 4
#define NKIT (DD / BKK)                 // 16
#define SROW 80
#define TILE_BYTES (BM * SROW)          // 10240
#define STAGE_BYTES (2 * TILE_BYTES)    // 20480
#define EP_PITCH 129
#define C2C_OFF (STAGES * STAGE_BYTES)  // 81920
#define GEMM_SMEM (C2C_OFF + 512)       // 82432

__global__ void __launch_bounds__(512) gemm_fused_k(float* __restrict__ ulbbase) {
    extern __shared__ __align__(16) char smem[];
    const uint32_t sbase = smem_u32(smem);

    const int tid  = threadIdx.x;
    const int wid  = tid >> 5;
    const int lane = tid & 31;
    const int wr   = wid & 3;      // warp row: 4 x 32 rows
    const int wc   = wid >> 2;     // warp col: 4 x 32 cols

    const int z  = blockIdx.z;
    const __nv_bfloat16* A = (z == 0) ? g_aqh : g_pqh;
    const __nv_bfloat16* B = g_suph + (size_t)z * NL * DD;
    const int m0 = blockIdx.y * BM;
    const int n0 = blockIdx.x * BN;
    const __nv_bfloat16* Abase = A + (size_t)m0 * DD;
    const __nv_bfloat16* Bbase = B + (size_t)n0 * DD;

    // load mapping: 512 threads, 1 A-chunk + 1 B-chunk (16B) each per stage
    const int r0 = tid >> 2;            // 0..127
    const int c0 = (tid & 3) * 8;       // chunk col in bf16

    float acc[2][4][4];
    #pragma unroll
    for (int mi = 0; mi < 2; mi++)
        #pragma unroll
        for (int ni = 0; ni < 4; ni++)
            #pragma unroll
            for (int q = 0; q < 4; q++) acc[mi][ni][q] = 0.f;

    #pragma unroll
    for (int s = 0; s < STAGES - 1; s++) {
        uint32_t sA = sbase + s * STAGE_BYTES;
        uint32_t sB = sA + TILE_BYTES;
        const __nv_bfloat16* Ak = Abase + s * BKK;
        const __nv_bfloat16* Bk = Bbase + s * BKK;
        CP_ASYNC16(sA + r0 * SROW + c0 * 2, Ak + (size_t)r0 * DD + c0);
        CP_ASYNC16(sB + r0 * SROW + c0 * 2, Bk + (size_t)r0 * DD + c0);
        CP_COMMIT();
    }

    const uint32_t aOff = (uint32_t)(wr * 32 + (lane & 15)) * SROW + (lane >> 4) * 16;
    const uint32_t bOff = (uint32_t)(wc * 32 + (lane & 7)) * SROW + ((lane >> 3) & 1) * 16;

    for (int kc = 0; kc < NKIT; kc++) {
        const int st = kc % STAGES;
        CP_WAIT(STAGES - 2);
        __syncthreads();

        const int pf = kc + STAGES - 1;
        if (pf < NKIT) {
            const int ps = pf % STAGES;
            uint32_t sA = sbase + ps * STAGE_BYTES;
            uint32_t sB = sA + TILE_BYTES;
            const __nv_bfloat16* Ak = Abase + pf * BKK;
            const __nv_bfloat16* Bk = Bbase + pf * BKK;
            CP_ASYNC16(sA + r0 * SROW + c0 * 2, Ak + (size_t)r0 * DD + c0);
            CP_ASYNC16(sB + r0 * SROW + c0 * 2, Bk + (size_t)r0 * DD + c0);
        }
        CP_COMMIT();

        const uint32_t sA = sbase + st * STAGE_BYTES;
        const uint32_t sB = sA + TILE_BYTES;
        #pragma unroll
        for (int kk = 0; kk < 2; kk++) {
            uint32_t aF[2][4], bF[4][2];
            #pragma unroll
            for (int mi = 0; mi < 2; mi++)
                ldsm_x4(aF[mi], sA + aOff + (uint32_t)mi * 16 * SROW + kk * 32);
            #pragma unroll
            for (int ni = 0; ni < 4; ni++)
                ldsm_x2(bF[ni], sB + bOff + (uint32_t)ni * 8 * SROW + kk * 32);
            #pragma unroll
            for (int mi = 0; mi < 2; mi++)
                #pragma unroll
                for (int ni = 0; ni < 4; ni++)
                    mma_bf16(acc[mi][ni], aF[mi], bF[ni]);
        }
    }

    // ---- epilogue: exp -> smem, per-row contiguous segment sums, atomics ----
    CP_WAIT(0);
    __syncthreads();

    float* ep    = (float*)smem;
    int*   c2c_s = (int*)(smem + C2C_OFF);

    const int ebr = wr * 32 + (lane >> 2);
    const int ebc = wc * 32 + (lane & 3) * 2;
    #pragma unroll
    for (int mi = 0; mi < 2; mi++) {
        #pragma unroll
        for (int ni = 0; ni < 4; ni++) {
            int rr = ebr + mi * 16, cc2 = ebc + ni * 8;
            ep[rr * EP_PITCH + cc2]           = __expf(acc[mi][ni][0] * INV_TAU);
            ep[rr * EP_PITCH + cc2 + 1]       = __expf(acc[mi][ni][1] * INV_TAU);
            ep[(rr + 8) * EP_PITCH + cc2]     = __expf(acc[mi][ni][2] * INV_TAU);
            ep[(rr + 8) * EP_PITCH + cc2 + 1] = __expf(acc[mi][ni][3] * INV_TAU);
        }
    }
    if (tid < BN) {
        const int* offs = g_offsets + z * (CC + 1);
        int v = n0 + tid;
        int lo = 0, hi = CC - 1;
        while (lo < hi) { int mid = (lo + hi + 1) >> 1; if (offs[mid] <= v) lo = mid; else hi = mid - 1; }
        c2c_s[tid] = lo;
    }
    __syncthreads();

    if (tid < BM) {
        float* orow = ulbbase + (size_t)z * NU * CC + (size_t)(m0 + tid) * CC;
        const float* er = ep + tid * EP_PITCH;
        float run = 0.f, rs = 0.f;
        int cls = c2c_s[0];
        #pragma unroll 4
        for (int j = 0; j < BN; j++) {
            int c2 = c2c_s[j];
            float e = er[j];
            if (c2 != cls) { atomicAdd(&orow[cls], run); run = 0.f; cls = c2; }
            run += e;
            rs  += e;
        }
        atomicAdd(&orow[cls], run);
        atomicAdd(&g_rowsum[z * NU + m0 + tid], rs);
    }
}

// ---- (7) normalize + zero empty classes --------------------------------------
__global__ void __launch_bounds__(256) normalize_k(float* __restrict__ ulbbase) {
    int u = blockIdx.x;
    int z = blockIdx.y;
    float inv = 1.0f / g_rowsum[z * NU + u];
    const int* offs = g_offsets + z * (CC + 1);
    float* orow = ulbbase + (size_t)z * NU * CC + (size_t)u * CC;
    for (int c = threadIdx.x; c < CC; c += 256) {
        float v = orow[c];
        orow[c] = (offs[c + 1] > offs[c]) ? v * inv : 0.f;
    }
}

// ---------------- launch ------------------------------------------------------
extern "C" void kernel_launch(void* const* d_in, const int* in_sizes, int n_in,
                              void* d_out, int out_size) {
    const float* anchor = (const float*)d_in[0];
    const float* pos    = (const float*)d_in[1];
    const float* lb     = (const float*)d_in[2];
    const float* oh     = (const float*)d_in[3];
    const float* lgx    = (const float*)d_in[4];
    float* out = (float*)d_out;

    const size_t nA  = (size_t)NU * DD;
    const size_t nP  = (size_t)NU * DD;
    const size_t nL  = (size_t)2 * NL * DD;
    const size_t nOH = (size_t)2 * NL * CC;
    const size_t nLG = (size_t)2 * NL * CC;
    size_t oA  = 0;
    size_t oP  = oA + nA;
    size_t oL  = oP + nP;
    size_t oOH = oL + nL;
    size_t oLG = oOH + nOH;
    size_t oU1 = oLG + nLG;

    // (1) one_hot copy + label extraction
    copy_labels_k<<<(2 * NL) / 8, 256>>>(oh, out + oOH);
    // (2) anchor+positive copy + normalize
    dim3 gq(NU / 8, 2);
    copy_norm_q_k<<<gq, 256>>>(anchor, pos, out + oA, out + oP);
    // (3) lb copy + lgx copy + zero ulb + zero rowsums
    copy_rest_k<<<(NTOT4 + 255) / 256, 256>>>(
        (const float4*)lb, (const float4*)lgx,
        (float4*)(out + oL), (float4*)(out + oLG), (float4*)(out + oU1));
    // (4) counting sort, one CTA per half
    sort_k<<<2, 1024>>>();
    // (5) supports: normalize in class-sorted order
    norm_sup_k<<<(2 * NL) / 8, 256>>>(lb);
    // (6) GEMM with fused exp + class partial-sum epilogue (512 thr / 16 warps)
    cudaFuncSetAttribute(gemm_fused_k, cudaFuncAttributeMaxDynamicSharedMemorySize, GEMM_SMEM);
    dim3 gg(NL / BN, NU / BM, 2);
    gemm_fused_k<<<gg, 512, GEMM_SMEM>>>(out + oU1);
    // (7) normalize + zero empty classes
    dim3 gn(NU, 2);
    normalize_k<<<gn, 256>>>(out + oU1);
}

// round 15
// speedup vs baseline: 1.4369x; 1.0127x over previous
#include <cuda_runtime.h>
#include <cuda_bf16.h>
#include <math_constants.h>
#include <cstdint>

// Problem constants
#define NU   8192
#define NL   8192     // per half
#define DD   512
#define CC   1000
#define INV_TAU 10.0f

// ---------------- device scratch ---------------------------------------------
__device__ __nv_bfloat16 g_aqh [NU * DD];
__device__ __nv_bfloat16 g_pqh [NU * DD];
__device__ __nv_bfloat16 g_suph[2 * NL * DD];     // class-sorted order
__device__ float g_rowsum[2 * NU];
__device__ int   g_labels[2 * NL];
__device__ int   g_offsets[2 * (CC + 1)];
__device__ int   g_perm[2 * NL];

// ---------------- PTX helpers -------------------------------------------------
__device__ __forceinline__ uint32_t smem_u32(const void* p) {
    uint32_t a;
    asm("{ .reg .u64 t; cvta.to.shared.u64 t, %1; cvt.u32.u64 %0, t; }" : "=r"(a) : "l"(p));
    return a;
}
#define CP_ASYNC16(s, g) asm volatile("cp.async.cg.shared.global [%0], [%1], 16;" :: "r"(s), "l"(g))
#define CP_COMMIT()      asm volatile("cp.async.commit_group;" ::: "memory")
#define CP_WAIT(n)       asm volatile("cp.async.wait_group %0;" :: "n"(n) : "memory")

__device__ __forceinline__ void ldsm_x4(uint32_t* r, uint32_t addr) {
    asm volatile("ldmatrix.sync.aligned.m8n8.x4.shared.b16 {%0,%1,%2,%3}, [%4];"
        : "=r"(r[0]), "=r"(r[1]), "=r"(r[2]), "=r"(r[3]) : "r"(addr));
}
__device__ __forceinline__ void ldsm_x2(uint32_t* r, uint32_t addr) {
    asm volatile("ldmatrix.sync.aligned.m8n8.x2.shared.b16 {%0,%1}, [%2];"
        : "=r"(r[0]), "=r"(r[1]) : "r"(addr));
}
__device__ __forceinline__ void mma_bf16(float* c, const uint32_t* a, const uint32_t* b) {
    asm volatile("mma.sync.aligned.m16n8k16.row.col.f32.bf16.bf16.f32 "
        "{%0,%1,%2,%3},{%4,%5,%6,%7},{%8,%9},{%0,%1,%2,%3};"
        : "+f"(c[0]), "+f"(c[1]), "+f"(c[2]), "+f"(c[3])
        : "r"(a[0]), "r"(a[1]), "r"(a[2]), "r"(a[3]), "r"(b[0]), "r"(b[1]));
}

// ---- (1) heterogeneous prep: copies + labels + q-normalize + zeroing ---------
// Block ranges (256 threads each, NO smem -> no occupancy interference):
//   [0, NB_OH)                 one_hot copy + label extract (8 rows/block, warp each)
//   [NB_OH, +NB_Q)             anchor/pos copy + l2 normalize (8 rows/block)
//   [.., +NB_R)                lb copy, lgx copy, zero ulb, zero rowsum (float4 stream)
#define NB_OH 2048
#define NB_Q  2048                   // 1024 per input
#define NL4 2097152u
#define NG4 4096000u
#define NZ4 4096000u
#define NR4 4096u
#define NTOT4 (NL4 + NG4 + NZ4 + NR4)
#define NB_R  ((NTOT4 + 255) / 256)
#define NB_PREP (NB_OH + NB_Q + NB_R)

__global__ void __launch_bounds__(256) prep_k(
    const float* __restrict__ anchor, const float* __restrict__ pos,
    const float* __restrict__ lb, const float* __restrict__ oh,
    const float* __restrict__ lgx,
    float* __restrict__ outA, float* __restrict__ outP,
    float* __restrict__ outL, float* __restrict__ outOH,
    float* __restrict__ outLG, float* __restrict__ outU)
{
    const int tid  = threadIdx.x;
    uint32_t bid = blockIdx.x;

    if (bid < NB_OH) {
        // one_hot copy + label extraction, warp per row
        int row  = bid * 8 + (tid >> 5);
        int lane = tid & 31;
        const float* r = oh + (size_t)row * CC;
        float* d = outOH + (size_t)row * CC;
        int lab = -1;
        for (int c = lane; c < CC; c += 32) {
            float v = r[c];
            d[c] = v;
            if (v > 0.5f) lab = c;
        }
        #pragma unroll
        for (int o = 16; o; o >>= 1) lab = max(lab, __shfl_xor_sync(0xffffffffu, lab, o));
        if (lane == 0) g_labels[row] = lab;
        return;
    }
    bid -= NB_OH;
    if (bid < NB_Q) {
        int sel  = bid >> 10;                    // 0: anchor, 1: pos
        int row  = (bid & 1023) * 8 + (tid >> 5);
        int lane = tid & 31;
        const float* src = (sel == 0) ? anchor : pos;
        float* dstcopy   = (sel == 0) ? outA : outP;
        __nv_bfloat16* nb = ((sel == 0) ? g_aqh : g_pqh) + (size_t)row * DD;
        const float4* s4 = (const float4*)(src + (size_t)row * DD);
        float4* d4 = (float4*)(dstcopy + (size_t)row * DD);
        float4 v[4];
        float acc = 0.f;
        #pragma unroll
        for (int i = 0; i < 4; i++) {
            v[i] = s4[lane + 32 * i];
            acc += v[i].x * v[i].x + v[i].y * v[i].y + v[i].z * v[i].z + v[i].w * v[i].w;
        }
        #pragma unroll
        for (int o = 16; o; o >>= 1) acc += __shfl_xor_sync(0xffffffffu, acc, o);
        float inv = 1.0f / fmaxf(sqrtf(acc), 1e-12f);
        #pragma unroll
        for (int i = 0; i < 4; i++) {
            d4[lane + 32 * i] = v[i];
            int c = (lane + 32 * i) * 4;
            nb[c + 0] = __float2bfloat16(v[i].x * inv);
            nb[c + 1] = __float2bfloat16(v[i].y * inv);
            nb[c + 2] = __float2bfloat16(v[i].z * inv);
            nb[c + 3] = __float2bfloat16(v[i].w * inv);
        }
        return;
    }
    bid -= NB_Q;
    {
        uint32_t i = bid * 256 + tid;
        if (i >= NTOT4) return;
        if (i < NL4) { ((float4*)outL)[i] = ((const float4*)lb)[i]; return; }
        i -= NL4;
        if (i < NG4) { ((float4*)outLG)[i] = ((const float4*)lgx)[i]; return; }
        i -= NG4;
        float4 z = make_float4(0.f, 0.f, 0.f, 0.f);
        if (i < NZ4) { ((float4*)outU)[i] = z; return; }
        i -= NZ4;
        ((float4*)g_rowsum)[i] = z;
    }
}

// ---- (2) single-CTA counting sort: counts + scan + scatter -------------------
__global__ void __launch_bounds__(1024) sort_k() {
    __shared__ int cnt[CC];
    __shared__ int cur[CC + 1];
    __shared__ int ws[32];
    int tid = threadIdx.x;
    int h   = blockIdx.x;
    for (int c = tid; c < CC; c += 1024) cnt[c] = 0;
    __syncthreads();
    const int* lab = g_labels + h * NL;
    for (int i = tid; i < NL; i += 1024) atomicAdd(&cnt[lab[i]], 1);
    __syncthreads();
    int lane = tid & 31, wid = tid >> 5;
    int v = (tid < CC) ? cnt[tid] : 0;
    int x = v;
    #pragma unroll
    for (int o = 1; o < 32; o <<= 1) {
        int y = __shfl_up_sync(0xffffffffu, x, o);
        if (lane >= o) x += y;
    }
    if (lane == 31) ws[wid] = x;
    __syncthreads();
    if (wid == 0) {
        int s = ws[lane];
        #pragma unroll
        for (int o = 1; o < 32; o <<= 1) {
            int y = __shfl_up_sync(0xffffffffu, s, o);
            if (lane >= o) s += y;
        }
        ws[lane] = s;
    }
    __syncthreads();
    int excl = x - v + (wid > 0 ? ws[wid - 1] : 0);
    if (tid < CC) {
        g_offsets[h * (CC + 1) + tid] = excl;
        cur[tid] = excl;
    }
    if (tid == CC) g_offsets[h * (CC + 1) + CC] = excl;
    __syncthreads();
    int* perm = g_perm + h * NL;
    for (int i = tid; i < NL; i += 1024) {
        int pos = atomicAdd(&cur[lab[i]], 1);
        perm[pos] = i;
    }
}

// ---- (3) supports: normalize, write in class-sorted (perm) order -------------
__global__ void norm_sup_k(const float* __restrict__ lb) {
    int row  = blockIdx.x * (blockDim.x >> 5) + (threadIdx.x >> 5);
    int lane = threadIdx.x & 31;
    if (row >= 2 * NL) return;
    int half = row / NL;
    int pos  = row - half * NL;
    int srow = half * NL + g_perm[half * NL + pos];
    const float* s = lb + (size_t)srow * DD;
    float v[16];
    float acc = 0.f;
    #pragma unroll
    for (int i = 0; i < 16; i++) { v[i] = s[lane + 32 * i]; acc += v[i] * v[i]; }
    #pragma unroll
    for (int o = 16; o; o >>= 1) acc += __shfl_xor_sync(0xffffffffu, acc, o);
    float inv = 1.0f / fmaxf(sqrtf(acc), 1e-12f);
    __nv_bfloat16* d = g_suph + (size_t)row * DD;
    #pragma unroll
    for (int i = 0; i < 16; i++) d[lane + 32 * i] = __float2bfloat16(v[i] * inv);
}

// ---- (4) GEMM + exp + class partial-sum epilogue, 512 threads / 16 warps -----
#define BM 128
#define BN 128
#define BKK 32
#define STAGES 4
#define NKIT (DD / BKK)                 // 16
#define SROW 80
#define TILE_BYTES (BM * SROW)          // 10240
#define STAGE_BYTES (2 * TILE_BYTES)    // 20480
#define EP_PITCH 129
#define C2C_OFF (STAGES * STAGE_BYTES)  // 81920
#define GEMM_SMEM (C2C_OFF + 512)       // 82432

__global__ void __launch_bounds__(512) gemm_fused_k(float* __restrict__ ulbbase) {
    extern __shared__ __align__(16) char smem[];
    const uint32_t sbase = smem_u32(smem);

    const int tid  = threadIdx.x;
    const int wid  = tid >> 5;
    const int lane = tid & 31;
    const int wr   = wid & 3;      // warp row: 4 x 32 rows
    const int wc   = wid >> 2;     // warp col: 4 x 32 cols

    const int z  = blockIdx.z;
    const __nv_bfloat16* A = (z == 0) ? g_aqh : g_pqh;
    const __nv_bfloat16* B = g_suph + (size_t)z * NL * DD;
    const int m0 = blockIdx.y * BM;
    const int n0 = blockIdx.x * BN;
    const __nv_bfloat16* Abase = A + (size_t)m0 * DD;
    const __nv_bfloat16* Bbase = B + (size_t)n0 * DD;

    const int r0 = tid >> 2;            // 0..127
    const int c0 = (tid & 3) * 8;       // chunk col in bf16

    float acc[2][4][4];
    #pragma unroll
    for (int mi = 0; mi < 2; mi++)
        #pragma unroll
        for (int ni = 0; ni < 4; ni++)
            #pragma unroll
            for (int q = 0; q < 4; q++) acc[mi][ni][q] = 0.f;

    #pragma unroll
    for (int s = 0; s < STAGES - 1; s++) {
        uint32_t sA = sbase + s * STAGE_BYTES;
        uint32_t sB = sA + TILE_BYTES;
        const __nv_bfloat16* Ak = Abase + s * BKK;
        const __nv_bfloat16* Bk = Bbase + s * BKK;
        CP_ASYNC16(sA + r0 * SROW + c0 * 2, Ak + (size_t)r0 * DD + c0);
        CP_ASYNC16(sB + r0 * SROW + c0 * 2, Bk + (size_t)r0 * DD + c0);
        CP_COMMIT();
    }

    const uint32_t aOff = (uint32_t)(wr * 32 + (lane & 15)) * SROW + (lane >> 4) * 16;
    const uint32_t bOff = (uint32_t)(wc * 32 + (lane & 7)) * SROW + ((lane >> 3) & 1) * 16;

    for (int kc = 0; kc < NKIT; kc++) {
        const int st = kc % STAGES;
        CP_WAIT(STAGES - 2);
        __syncthreads();

        const int pf = kc + STAGES - 1;
        if (pf < NKIT) {
            const int ps = pf % STAGES;
            uint32_t sA = sbase + ps * STAGE_BYTES;
            uint32_t sB = sA + TILE_BYTES;
            const __nv_bfloat16* Ak = Abase + pf * BKK;
            const __nv_bfloat16* Bk = Bbase + pf * BKK;
            CP_ASYNC16(sA + r0 * SROW + c0 * 2, Ak + (size_t)r0 * DD + c0);
            CP_ASYNC16(sB + r0 * SROW + c0 * 2, Bk + (size_t)r0 * DD + c0);
        }
        CP_COMMIT();

        const uint32_t sA = sbase + st * STAGE_BYTES;
        const uint32_t sB = sA + TILE_BYTES;
        #pragma unroll
        for (int kk = 0; kk < 2; kk++) {
            uint32_t aF[2][4], bF[4][2];
            #pragma unroll
            for (int mi = 0; mi < 2; mi++)
                ldsm_x4(aF[mi], sA + aOff + (uint32_t)mi * 16 * SROW + kk * 32);
            #pragma unroll
            for (int ni = 0; ni < 4; ni++)
                ldsm_x2(bF[ni], sB + bOff + (uint32_t)ni * 8 * SROW + kk * 32);
            #pragma unroll
            for (int mi = 0; mi < 2; mi++)
                #pragma unroll
                for (int ni = 0; ni < 4; ni++)
                    mma_bf16(acc[mi][ni], aF[mi], bF[ni]);
        }
    }

    // ---- epilogue: exp -> smem, per-row contiguous segment sums, RED atomics --
    CP_WAIT(0);
    __syncthreads();

    float* ep    = (float*)smem;
    int*   c2c_s = (int*)(smem + C2C_OFF);

    const int ebr = wr * 32 + (lane >> 2);
    const int ebc = wc * 32 + (lane & 3) * 2;
    #pragma unroll
    for (int mi = 0; mi < 2; mi++) {
        #pragma unroll
        for (int ni = 0; ni < 4; ni++) {
            int rr = ebr + mi * 16, cc2 = ebc + ni * 8;
            ep[rr * EP_PITCH + cc2]           = __expf(acc[mi][ni][0] * INV_TAU);
            ep[rr * EP_PITCH + cc2 + 1]       = __expf(acc[mi][ni][1] * INV_TAU);
            ep[(rr + 8) * EP_PITCH + cc2]     = __expf(acc[mi][ni][2] * INV_TAU);
            ep[(rr + 8) * EP_PITCH + cc2 + 1] = __expf(acc[mi][ni][3] * INV_TAU);
        }
    }
    if (tid < BN) {
        const int* offs = g_offsets + z * (CC + 1);
        int v = n0 + tid;
        int lo = 0, hi = CC - 1;
        while (lo < hi) { int mid = (lo + hi + 1) >> 1; if (offs[mid] <= v) lo = mid; else hi = mid - 1; }
        c2c_s[tid] = lo;
    }
    __syncthreads();

    if (tid < BM) {
        float* orow = ulbbase + (size_t)z * NU * CC + (size_t)(m0 + tid) * CC;
        const float* er = ep + tid * EP_PITCH;
        float run = 0.f, rs = 0.f;
        int cls = c2c_s[0];
        #pragma unroll 4
        for (int j = 0; j < BN; j++) {
            int c2 = c2c_s[j];
            float e = er[j];
            if (c2 != cls) { atomicAdd(&orow[cls], run); run = 0.f; cls = c2; }
            run += e;
            rs  += e;
        }
        atomicAdd(&orow[cls], run);
        atomicAdd(&g_rowsum[z * NU + m0 + tid], rs);
    }
}

// ---- (5) normalize + zero empty classes --------------------------------------
__global__ void __launch_bounds__(256) normalize_k(float* __restrict__ ulbbase) {
    int u = blockIdx.x;
    int z = blockIdx.y;
    float inv = 1.0f / g_rowsum[z * NU + u];
    const int* offs = g_offsets + z * (CC + 1);
    float* orow = ulbbase + (size_t)z * NU * CC + (size_t)u * CC;
    for (int c = threadIdx.x; c < CC; c += 256) {
        float v = orow[c];
        orow[c] = (offs[c + 1] > offs[c]) ? v * inv : 0.f;
    }
}

// ---------------- launch ------------------------------------------------------
extern "C" void kernel_launch(void* const* d_in, const int* in_sizes, int n_in,
                              void* d_out, int out_size) {
    const float* anchor = (const float*)d_in[0];
    const float* pos    = (const float*)d_in[1];
    const float* lb     = (const float*)d_in[2];
    const float* oh     = (const float*)d_in[3];
    const float* lgx    = (const float*)d_in[4];
    float* out = (float*)d_out;

    const size_t nA  = (size_t)NU * DD;
    const size_t nP  = (size_t)NU * DD;
    const size_t nL  = (size_t)2 * NL * DD;
    const size_t nOH = (size_t)2 * NL * CC;
    const size_t nLG = (size_t)2 * NL * CC;
    size_t oA  = 0;
    size_t oP  = oA + nA;
    size_t oL  = oP + nP;
    size_t oOH = oL + nL;
    size_t oLG = oOH + nOH;
    size_t oU1 = oLG + nLG;

    // (1) mega prep: all copies + labels + q-normalize + zeroing
    prep_k<<<NB_PREP, 256>>>(anchor, pos, lb, oh, lgx,
                             out + oA, out + oP, out + oL, out + oOH,
                             out + oLG, out + oU1);
    // (2) counting sort, one CTA per half
    sort_k<<<2, 1024>>>();
    // (3) supports: normalize in class-sorted order
    norm_sup_k<<<(2 * NL) / 8, 256>>>(lb);
    // (4) GEMM with fused exp + class partial-sum epilogue (512 thr / 16 warps)
    cudaFuncSetAttribute(gemm_fused_k, cudaFuncAttributeMaxDynamicSharedMemorySize, GEMM_SMEM);
    dim3 gg(NL / BN, NU / BM, 2);
    gemm_fused_k<<<gg, 512, GEMM_SMEM>>>(out + oU1);
    // (5) normalize + zero empty classes
    dim3 gn(NU, 2);
    normalize_k<<<gn, 256>>>(out + oU1);
}

// round 16
// speedup vs baseline: 1.4991x; 1.0433x over previous
#include <cuda_runtime.h>
#include <cuda_bf16.h>
#include <math_constants.h>
#include <cstdint>

// Problem constants
#define NU   8192
#define NL   8192     // per half
#define DD   512
#define CC   1000
#define INV_TAU 10.0f

// ---------------- device scratch ---------------------------------------------
__device__ __nv_bfloat16 g_aqh [NU * DD];
__device__ __nv_bfloat16 g_pqh [NU * DD];
__device__ __nv_bfloat16 g_suph[2 * NL * DD];     // class-sorted order
__device__ float g_rowsum[2 * NU];
__device__ int   g_labels[2 * NL];
__device__ int   g_offsets[2 * (CC + 1)];
__device__ int   g_perm[2 * NL];

// ---------------- PTX helpers -------------------------------------------------
__device__ __forceinline__ uint32_t smem_u32(const void* p) {
    uint32_t a;
    asm("{ .reg .u64 t; cvta.to.shared.u64 t, %1; cvt.u32.u64 %0, t; }" : "=r"(a) : "l"(p));
    return a;
}
#define CP_ASYNC16(s, g) asm volatile("cp.async.cg.shared.global [%0], [%1], 16;" :: "r"(s), "l"(g))
#define CP_COMMIT()      asm volatile("cp.async.commit_group;" ::: "memory")
#define CP_WAIT(n)       asm volatile("cp.async.wait_group %0;" :: "n"(n) : "memory")

__device__ __forceinline__ void ldsm_x4(uint32_t* r, uint32_t addr) {
    asm volatile("ldmatrix.sync.aligned.m8n8.x4.shared.b16 {%0,%1,%2,%3}, [%4];"
        : "=r"(r[0]), "=r"(r[1]), "=r"(r[2]), "=r"(r[3]) : "r"(addr));
}
__device__ __forceinline__ void mma_bf16(float* c, const uint32_t* a, const uint32_t* b) {
    asm volatile("mma.sync.aligned.m16n8k16.row.col.f32.bf16.bf16.f32 "
        "{%0,%1,%2,%3},{%4,%5,%6,%7},{%8,%9},{%0,%1,%2,%3};"
        : "+f"(c[0]), "+f"(c[1]), "+f"(c[2]), "+f"(c[3])
        : "r"(a[0]), "r"(a[1]), "r"(a[2]), "r"(a[3]), "r"(b[0]), "r"(b[1]));
}

// ---- (1) heterogeneous prep: copies + labels + q-normalize + zeroing ---------
#define NB_OH 2048
#define NB_Q  2048                   // 1024 per input
#define NL4 2097152u
#define NG4 4096000u
#define NZ4 4096000u
#define NR4 4096u
#define NTOT4 (NL4 + NG4 + NZ4 + NR4)
#define NB_R  ((NTOT4 + 255) / 256)
#define NB_PREP (NB_OH + NB_Q + NB_R)

__global__ void __launch_bounds__(256) prep_k(
    const float* __restrict__ anchor, const float* __restrict__ pos,
    const float* __restrict__ lb, const float* __restrict__ oh,
    const float* __restrict__ lgx,
    float* __restrict__ outA, float* __restrict__ outP,
    float* __restrict__ outL, float* __restrict__ outOH,
    float* __restrict__ outLG, float* __restrict__ outU)
{
    const int tid  = threadIdx.x;
    uint32_t bid = blockIdx.x;

    if (bid < NB_OH) {
        int row  = bid * 8 + (tid >> 5);
        int lane = tid & 31;
        const float* r = oh + (size_t)row * CC;
        float* d = outOH + (size_t)row * CC;
        int lab = -1;
        for (int c = lane; c < CC; c += 32) {
            float v = r[c];
            d[c] = v;
            if (v > 0.5f) lab = c;
        }
        #pragma unroll
        for (int o = 16; o; o >>= 1) lab = max(lab, __shfl_xor_sync(0xffffffffu, lab, o));
        if (lane == 0) g_labels[row] = lab;
        return;
    }
    bid -= NB_OH;
    if (bid < NB_Q) {
        int sel  = bid >> 10;
        int row  = (bid & 1023) * 8 + (tid >> 5);
        int lane = tid & 31;
        const float* src = (sel == 0) ? anchor : pos;
        float* dstcopy   = (sel == 0) ? outA : outP;
        __nv_bfloat16* nb = ((sel == 0) ? g_aqh : g_pqh) + (size_t)row * DD;
        const float4* s4 = (const float4*)(src + (size_t)row * DD);
        float4* d4 = (float4*)(dstcopy + (size_t)row * DD);
        float4 v[4];
        float acc = 0.f;
        #pragma unroll
        for (int i = 0; i < 4; i++) {
            v[i] = s4[lane + 32 * i];
            acc += v[i].x * v[i].x + v[i].y * v[i].y + v[i].z * v[i].z + v[i].w * v[i].w;
        }
        #pragma unroll
        for (int o = 16; o; o >>= 1) acc += __shfl_xor_sync(0xffffffffu, acc, o);
        float inv = 1.0f / fmaxf(sqrtf(acc), 1e-12f);
        #pragma unroll
        for (int i = 0; i < 4; i++) {
            d4[lane + 32 * i] = v[i];
            int c = (lane + 32 * i) * 4;
            nb[c + 0] = __float2bfloat16(v[i].x * inv);
            nb[c + 1] = __float2bfloat16(v[i].y * inv);
            nb[c + 2] = __float2bfloat16(v[i].z * inv);
            nb[c + 3] = __float2bfloat16(v[i].w * inv);
        }
        return;
    }
    bid -= NB_Q;
    {
        uint32_t i = bid * 256 + tid;
        if (i >= NTOT4) return;
        if (i < NL4) { ((float4*)outL)[i] = ((const float4*)lb)[i]; return; }
        i -= NL4;
        if (i < NG4) { ((float4*)outLG)[i] = ((const float4*)lgx)[i]; return; }
        i -= NG4;
        float4 z = make_float4(0.f, 0.f, 0.f, 0.f);
        if (i < NZ4) { ((float4*)outU)[i] = z; return; }
        i -= NZ4;
        ((float4*)g_rowsum)[i] = z;
    }
}

// ---- (2) single-CTA counting sort: counts + scan + scatter -------------------
__global__ void __launch_bounds__(1024) sort_k() {
    __shared__ int cnt[CC];
    __shared__ int cur[CC + 1];
    __shared__ int ws[32];
    int tid = threadIdx.x;
    int h   = blockIdx.x;
    for (int c = tid; c < CC; c += 1024) cnt[c] = 0;
    __syncthreads();
    const int* lab = g_labels + h * NL;
    for (int i = tid; i < NL; i += 1024) atomicAdd(&cnt[lab[i]], 1);
    __syncthreads();
    int lane = tid & 31, wid = tid >> 5;
    int v = (tid < CC) ? cnt[tid] : 0;
    int x = v;
    #pragma unroll
    for (int o = 1; o < 32; o <<= 1) {
        int y = __shfl_up_sync(0xffffffffu, x, o);
        if (lane >= o) x += y;
    }
    if (lane == 31) ws[wid] = x;
    __syncthreads();
    if (wid == 0) {
        int s = ws[lane];
        #pragma unroll
        for (int o = 1; o < 32; o <<= 1) {
            int y = __shfl_up_sync(0xffffffffu, s, o);
            if (lane >= o) s += y;
        }
        ws[lane] = s;
    }
    __syncthreads();
    int excl = x - v + (wid > 0 ? ws[wid - 1] : 0);
    if (tid < CC) {
        g_offsets[h * (CC + 1) + tid] = excl;
        cur[tid] = excl;
    }
    if (tid == CC) g_offsets[h * (CC + 1) + CC] = excl;
    __syncthreads();
    int* perm = g_perm + h * NL;
    for (int i = tid; i < NL; i += 1024) {
        int pos = atomicAdd(&cur[lab[i]], 1);
        perm[pos] = i;
    }
}

// ---- (3) supports: normalize, write in class-sorted (perm) order -------------
__global__ void norm_sup_k(const float* __restrict__ lb) {
    int row  = blockIdx.x * (blockDim.x >> 5) + (threadIdx.x >> 5);
    int lane = threadIdx.x & 31;
    if (row >= 2 * NL) return;
    int half = row / NL;
    int pos  = row - half * NL;
    int srow = half * NL + g_perm[half * NL + pos];
    const float* s = lb + (size_t)srow * DD;
    float v[16];
    float acc = 0.f;
    #pragma unroll
    for (int i = 0; i < 16; i++) { v[i] = s[lane + 32 * i]; acc += v[i] * v[i]; }
    #pragma unroll
    for (int o = 16; o; o >>= 1) acc += __shfl_xor_sync(0xffffffffu, acc, o);
    float inv = 1.0f / fmaxf(sqrtf(acc), 1e-12f);
    __nv_bfloat16* d = g_suph + (size_t)row * DD;
    #pragma unroll
    for (int i = 0; i < 16; i++) d[lane + 32 * i] = __float2bfloat16(v[i] * inv);
}

// ---- (4) GEMM + exp + class partial-sum epilogue, 512 threads / 16 warps -----
// All smem fragment loads via ldsm_x4 (LDSM issue floor is width-independent).
#define BM 128
#define BN 128
#define BKK 32
#define STAGES 4
#define NKIT (DD / BKK)                 // 16
#define SROW 80
#define TILE_BYTES (BM * SROW)          // 10240
#define STAGE_BYTES (2 * TILE_BYTES)    // 20480
#define EP_PITCH 129
#define C2C_OFF (STAGES * STAGE_BYTES)  // 81920
#define GEMM_SMEM (C2C_OFF + 512)       // 82432

__global__ void __launch_bounds__(512) gemm_fused_k(float* __restrict__ ulbbase) {
    extern __shared__ __align__(16) char smem[];
    const uint32_t sbase = smem_u32(smem);

    const int tid  = threadIdx.x;
    const int wid  = tid >> 5;
    const int lane = tid & 31;
    const int wr   = wid & 3;      // warp row: 4 x 32 rows
    const int wc   = wid >> 2;     // warp col: 4 x 32 cols

    const int z  = blockIdx.z;
    const __nv_bfloat16* A = (z == 0) ? g_aqh : g_pqh;
    const __nv_bfloat16* B = g_suph + (size_t)z * NL * DD;
    const int m0 = blockIdx.y * BM;
    const int n0 = blockIdx.x * BN;
    const __nv_bfloat16* Abase = A + (size_t)m0 * DD;
    const __nv_bfloat16* Bbase = B + (size_t)n0 * DD;

    const int r0 = tid >> 2;            // 0..127
    const int c0 = (tid & 3) * 8;       // chunk col in bf16

    float acc[2][4][4];
    #pragma unroll
    for (int mi = 0; mi < 2; mi++)
        #pragma unroll
        for (int ni = 0; ni < 4; ni++)
            #pragma unroll
            for (int q = 0; q < 4; q++) acc[mi][ni][q] = 0.f;

    #pragma unroll
    for (int s = 0; s < STAGES - 1; s++) {
        uint32_t sA = sbase + s * STAGE_BYTES;
        uint32_t sB = sA + TILE_BYTES;
        const __nv_bfloat16* Ak = Abase + s * BKK;
        const __nv_bfloat16* Bk = Bbase + s * BKK;
        CP_ASYNC16(sA + r0 * SROW + c0 * 2, Ak + (size_t)r0 * DD + c0);
        CP_ASYNC16(sB + r0 * SROW + c0 * 2, Bk + (size_t)r0 * DD + c0);
        CP_COMMIT();
    }

    // both A and B fragment addresses use the 16-row x4 pattern (conflict-free)
    const uint32_t aOff = (uint32_t)(wr * 32 + (lane & 15)) * SROW + (lane >> 4) * 16;
    const uint32_t bOff = (uint32_t)(wc * 32 + (lane & 15)) * SROW + (lane >> 4) * 16;

    for (int kc = 0; kc < NKIT; kc++) {
        const int st = kc % STAGES;
        CP_WAIT(STAGES - 2);
        __syncthreads();

        const int pf = kc + STAGES - 1;
        if (pf < NKIT) {
            const int ps = pf % STAGES;
            uint32_t sA = sbase + ps * STAGE_BYTES;
            uint32_t sB = sA + TILE_BYTES;
            const __nv_bfloat16* Ak = Abase + pf * BKK;
            const __nv_bfloat16* Bk = Bbase + pf * BKK;
            CP_ASYNC16(sA + r0 * SROW + c0 * 2, Ak + (size_t)r0 * DD + c0);
            CP_ASYNC16(sB + r0 * SROW + c0 * 2, Bk + (size_t)r0 * DD + c0);
        }
        CP_COMMIT();

        const uint32_t sA = sbase + st * STAGE_BYTES;
        const uint32_t sB = sA + TILE_BYTES;
        #pragma unroll
        for (int kk = 0; kk < 2; kk++) {
            uint32_t aF[2][4], bQ[2][4];
            #pragma unroll
            for (int mi = 0; mi < 2; mi++)
                ldsm_x4(aF[mi], sA + aOff + (uint32_t)mi * 16 * SROW + kk * 32);
            #pragma unroll
            for (int nj = 0; nj < 2; nj++)
                ldsm_x4(bQ[nj], sB + bOff + (uint32_t)nj * 16 * SROW + kk * 32);
            // x4 of B 16x16: m0=rows0-7/k0-7, m1=rows8-15/k0-7, m2=rows0-7/k8-15, m3=rows8-15/k8-15
            #pragma unroll
            for (int mi = 0; mi < 2; mi++) {
                #pragma unroll
                for (int nj = 0; nj < 2; nj++) {
                    uint32_t b0[2] = { bQ[nj][0], bQ[nj][2] };
                    uint32_t b1[2] = { bQ[nj][1], bQ[nj][3] };
                    mma_bf16(acc[mi][2 * nj + 0], aF[mi], b0);
                    mma_bf16(acc[mi][2 * nj + 1], aF[mi], b1);
                }
            }
        }
    }

    // ---- epilogue: exp -> smem, per-row contiguous segment sums, atomics ----
    CP_WAIT(0);
    __syncthreads();

    float* ep    = (float*)smem;
    int*   c2c_s = (int*)(smem + C2C_OFF);

    const int ebr = wr * 32 + (lane >> 2);
    const int ebc = wc * 32 + (lane & 3) * 2;
    #pragma unroll
    for (int mi = 0; mi < 2; mi++) {
        #pragma unroll
        for (int ni = 0; ni < 4; ni++) {
            int rr = ebr + mi * 16, cc2 = ebc + ni * 8;
            ep[rr * EP_PITCH + cc2]           = __expf(acc[mi][ni][0] * INV_TAU);
            ep[rr * EP_PITCH + cc2 + 1]       = __expf(acc[mi][ni][1] * INV_TAU);
            ep[(rr + 8) * EP_PITCH + cc2]     = __expf(acc[mi][ni][2] * INV_TAU);
            ep[(rr + 8) * EP_PITCH + cc2 + 1] = __expf(acc[mi][ni][3] * INV_TAU);
        }
    }
    if (tid < BN) {
        const int* offs = g_offsets + z * (CC + 1);
        int v = n0 + tid;
        int lo = 0, hi = CC - 1;
        while (lo < hi) { int mid = (lo + hi + 1) >> 1; if (offs[mid] <= v) lo = mid; else hi = mid - 1; }
        c2c_s[tid] = lo;
    }
    __syncthreads();

    if (tid < BM) {
        float* orow = ulbbase + (size_t)z * NU * CC + (size_t)(m0 + tid) * CC;
        const float* er = ep + tid * EP_PITCH;
        float run = 0.f, rs = 0.f;
        int cls = c2c_s[0];
        #pragma unroll 4
        for (int j = 0; j < BN; j++) {
            int c2 = c2c_s[j];
            float e = er[j];
            if (c2 != cls) { atomicAdd(&orow[cls], run); run = 0.f; cls = c2; }
            run += e;
            rs  += e;
        }
        atomicAdd(&orow[cls], run);
        atomicAdd(&g_rowsum[z * NU + m0 + tid], rs);
    }
}

// ---- (5) normalize + zero empty classes --------------------------------------
__global__ void __launch_bounds__(256) normalize_k(float* __restrict__ ulbbase) {
    int u = blockIdx.x;
    int z = blockIdx.y;
    float inv = 1.0f / g_rowsum[z * NU + u];
    const int* offs = g_offsets + z * (CC + 1);
    float* orow = ulbbase + (size_t)z * NU * CC + (size_t)u * CC;
    for (int c = threadIdx.x; c < CC; c += 256) {
        float v = orow[c];
        orow[c] = (offs[c + 1] > offs[c]) ? v * inv : 0.f;
    }
}

// ---------------- launch ------------------------------------------------------
extern "C" void kernel_launch(void* const* d_in, const int* in_sizes, int n_in,
                              void* d_out, int out_size) {
    const float* anchor = (const float*)d_in[0];
    const float* pos    = (const float*)d_in[1];
    const float* lb     = (const float*)d_in[2];
    const float* oh     = (const float*)d_in[3];
    const float* lgx    = (const float*)d_in[4];
    float* out = (float*)d_out;

    const size_t nA  = (size_t)NU * DD;
    const size_t nP  = (size_t)NU * DD;
    const size_t nL  = (size_t)2 * NL * DD;
    const size_t nOH = (size_t)2 * NL * CC;
    const size_t nLG = (size_t)2 * NL * CC;
    size_t oA  = 0;
    size_t oP  = oA + nA;
    size_t oL  = oP + nP;
    size_t oOH = oL + nL;
    size_t oLG = oOH + nOH;
    size_t oU1 = oLG + nLG;

    // (1) mega prep: all copies + labels + q-normalize + zeroing
    prep_k<<<NB_PREP, 256>>>(anchor, pos, lb, oh, lgx,
                             out + oA, out + oP, out + oL, out + oOH,
                             out + oLG, out + oU1);
    // (2) counting sort, one CTA per half
    sort_k<<<2, 1024>>>();
    // (3) supports: normalize in class-sorted order
    norm_sup_k<<<(2 * NL) / 8, 256>>>(lb);
    // (4) GEMM with fused exp + class partial-sum epilogue (512 thr / 16 warps)
    cudaFuncSetAttribute(gemm_fused_k, cudaFuncAttributeMaxDynamicSharedMemorySize, GEMM_SMEM);
    dim3 gg(NL / BN, NU / BM, 2);
    gemm_fused_k<<<gg, 512, GEMM_SMEM>>>(out + oU1);
    // (5) normalize + zero empty classes
    dim3 gn(NU, 2);
    normalize_k<<<gn, 256>>>(out + oU1);
}